// round 2
// baseline (speedup 1.0000x reference)
#include <cuda_runtime.h>

namespace {
constexpr int K      = 9;
constexpr int NB     = 64;
constexpr int NH     = 32;
constexpr int NW     = 32;
constexpr int NCELL  = NH * NW;        // 1024
constexpr int NT     = 50;
constexpr int NLAB   = 2 * K + 3;      // 21
constexpr int CH     = 2 * K + 2;      // 20 channels (2K coords + conf + class)
constexpr float THR  = 80.0f;
constexpr float IMW  = 640.0f;
constexpr float IMH  = 480.0f;
constexpr float SIL  = 0.6f;
constexpr float OBJ  = 5.0f;
}

__global__ void rl_zero_kernel(float* o) { o[0] = 0.0f; }

__global__ __launch_bounds__(256) void region_loss_kernel(
    const float* __restrict__ out,
    const float* __restrict__ tgt,
    const int*   __restrict__ epoch_p,
    float*       __restrict__ loss)
{
    __shared__ float sgt[NT][2 * K];   // target corner coords (normalized)
    __shared__ int   scell[NT];        // target cell index or -1 (OOB/dropped)
    __shared__ float sbx0[NT], sbx1[NT], sby0[NT], sby1[NT];  // gt corner bboxes
    __shared__ int   s_nvalid;
    __shared__ float swarp[8];

    const int b    = blockIdx.y;
    const int tid  = threadIdx.x;
    const int cell = blockIdx.x * 256 + tid;   // 0..1023

    // ---- stage targets for this batch ----
    const float* tb = tgt + (size_t)b * (NT * NLAB);
    for (int idx = tid; idx < NT * 2 * K; idx += 256) {
        int t = idx / (2 * K), c = idx - t * (2 * K);
        sgt[t][c] = tb[t * NLAB + 1 + c];
    }
    __syncthreads();
    if (tid == 0) {
        // valid = cumprod(x0 != 0) > 0  ->  length of nonzero prefix
        int nv = 0;
        while (nv < NT && sgt[nv][0] != 0.0f) nv++;
        s_nvalid = nv;
    }
    if (tid < NT) {
        float mnx = sgt[tid][0], mxx = mnx, mny = sgt[tid][1], mxy = mny;
        #pragma unroll
        for (int k = 1; k < K; k++) {
            float x = sgt[tid][2 * k], y = sgt[tid][2 * k + 1];
            mnx = fminf(mnx, x); mxx = fmaxf(mxx, x);
            mny = fminf(mny, y); mxy = fmaxf(mxy, y);
        }
        sbx0[tid] = mnx; sbx1[tid] = mxx; sby0[tid] = mny; sby1[tid] = mxy;
        int gi0 = (int)floorf(sgt[tid][0] * (float)NW);
        int gj0 = (int)floorf(sgt[tid][1] * (float)NH);
        // JAX scatter drops OOB updates
        scell[tid] = (gi0 >= 0 && gi0 < NW && gj0 >= 0 && gj0 < NH)
                         ? gj0 * NW + gi0 : -1;
    }
    __syncthreads();

    const int  nvalid  = s_nvalid;
    const bool do_conf = (epoch_p ? __ldg(epoch_p) : 20) > 15;
    const float i_f = (float)(cell & (NW - 1));
    const float j_f = (float)(cell >> 5);

    // ---- per-cell predictions (coalesced channel-strided loads) ----
    const float* ob = out + (size_t)(b * CH) * NCELL + cell;
    float xs[K], ys[K], pcx[K], pcy[K];
    #pragma unroll
    for (int k = 0; k < K; k++) {
        xs[k] = ob[(2 * k) * NCELL];
        ys[k] = ob[(2 * k + 1) * NCELL];
    }
    float confp = ob[(2 * K) * NCELL];
    xs[0]  = 1.0f / (1.0f + __expf(-xs[0]));
    ys[0]  = 1.0f / (1.0f + __expf(-ys[0]));
    confp  = 1.0f / (1.0f + __expf(-confp));

    float pminx = 1e30f, pmaxx = -1e30f, pminy = 1e30f, pmaxy = -1e30f;
    #pragma unroll
    for (int k = 0; k < K; k++) {
        pcx[k] = (xs[k] + i_f) * (1.0f / NW);
        pcy[k] = (ys[k] + j_f) * (1.0f / NH);
        pminx = fminf(pminx, pcx[k]); pmaxx = fmaxf(pmaxx, pcx[k]);
        pminy = fminf(pminy, pcy[k]); pmaxy = fmaxf(pmaxy, pcy[k]);
    }

    const float inv_den = 1.0f / (__expf(2.0f) - 1.0f + 1e-5f);
    const float XB = THR / IMW;   // 0.125
    const float YB = THR / IMH;   // 0.1667

    // ---- silent-zone max-conf over valid targets, with exact-zero prune ----
    float cur  = 0.0f;
    int   thit = -1;
    for (int t = 0; t < nvalid; t++) {
        if (scell[t] == cell) thit = t;
        // if corner bboxes are separated by >= TH in either scaled axis,
        // every per-corner distance >= TH -> contribution exactly 0
        float sepx = fmaxf(sbx0[t] - pmaxx, pminx - sbx1[t]);
        float sepy = fmaxf(sby0[t] - pmaxy, pminy - sby1[t]);
        if (sepx >= XB || sepy >= YB) continue;
        float acc = 0.0f;
        #pragma unroll
        for (int k = 0; k < K; k++) {
            float dx = (sgt[t][2 * k]     - pcx[k]) * IMW;
            float dy = (sgt[t][2 * k + 1] - pcy[k]) * IMH;
            float d2 = dx * dx + dy * dy;
            if (d2 < THR * THR)
                acc += __expf(2.0f - sqrtf(d2) * (2.0f / THR)) - 1.0f;
        }
        cur = fmaxf(cur, acc * inv_den * (1.0f / (float)K));
    }

    // ---- per-cell loss ----
    float lcl = 0.0f;
    if (thit >= 0) {
        // target cell: coord loss + OBJ-weighted conf loss vs conf_gt
        float gx0 = floorf(sgt[thit][0] * (float)NW);
        float gy0 = floorf(sgt[thit][1] * (float)NH);
        float acc = 0.0f;
        #pragma unroll
        for (int k = 0; k < K; k++) {
            float gxk = sgt[thit][2 * k]     * (float)NW;
            float gyk = sgt[thit][2 * k + 1] * (float)NH;
            float ex  = xs[k] - (gxk - gx0);
            float ey  = ys[k] - (gyk - gy0);
            lcl += 0.5f * (ex * ex + ey * ey);
            float dx = (sgt[thit][2 * k]     - pcx[k]) * IMW;
            float dy = (sgt[thit][2 * k + 1] - pcy[k]) * IMH;
            float d2 = dx * dx + dy * dy;
            if (d2 < THR * THR)
                acc += __expf(2.0f - sqrtf(d2) * (2.0f / THR)) - 1.0f;
        }
        if (do_conf) {
            float tconf = acc * inv_den * (1.0f / (float)K);
            float e = confp - tconf;
            lcl += 0.5f * OBJ * e * e;
        }
    } else if (do_conf) {
        float mask = (cur > SIL) ? 0.0f : 1.0f;   // silent vs NOOBJ
        lcl += 0.5f * mask * confp * confp;       // tconf = 0 here
    }

    // ---- block reduction, one atomic per block ----
    #pragma unroll
    for (int o = 16; o > 0; o >>= 1)
        lcl += __shfl_xor_sync(0xffffffffu, lcl, o);
    if ((tid & 31) == 0) swarp[tid >> 5] = lcl;
    __syncthreads();
    if (tid < 8) {
        float v = swarp[tid];
        #pragma unroll
        for (int o = 4; o > 0; o >>= 1)
            v += __shfl_xor_sync(0xffu, v, o);
        if (tid == 0) atomicAdd(loss, v);
    }
}

extern "C" void kernel_launch(void* const* d_in, const int* in_sizes, int n_in,
                              void* d_out, int out_size)
{
    const float* output = (const float*)d_in[0];
    const float* target = (const float*)d_in[1];
    const int*   epoch  = (n_in > 2) ? (const int*)d_in[2] : nullptr;
    float* loss = (float*)d_out;

    rl_zero_kernel<<<1, 1>>>(loss);
    dim3 grid(NCELL / 256, NB);   // (4, 64)
    region_loss_kernel<<<grid, 256>>>(output, target, epoch, loss);
    (void)in_sizes; (void)out_size;
}

// round 3
// speedup vs baseline: 1.1530x; 1.1530x over previous
#include <cuda_runtime.h>

namespace {
constexpr int K     = 9;
constexpr int NB    = 64;
constexpr int NH    = 32;
constexpr int NW    = 32;
constexpr int NCELL = NH * NW;       // 1024
constexpr int NT    = 50;
constexpr int NLAB  = 2 * K + 3;     // 21
constexpr int CH    = 2 * K + 2;     // 20
constexpr float THR = 80.0f;
constexpr float IMW = 640.0f;
constexpr float IMH = 480.0f;
constexpr float SIL = 0.6f;
constexpr float OBJ = 5.0f;
constexpr int   NBLK = 256;          // 4 cell-chunks x 64 batches
constexpr float CELLW = IMW / NW;    // 20 px
constexpr float CELLH = IMH / NH;    // 15 px
}

__device__ float        g_partials[NBLK];
__device__ unsigned int g_count = 0;

__global__ __launch_bounds__(256) void region_loss_kernel(
    const float* __restrict__ out,
    const float* __restrict__ tgt,
    const int*   __restrict__ epoch_p,
    float*       __restrict__ loss)
{
    __shared__ float sX[NT][K], sY[NT][K];         // gt corners, pixel space
    __shared__ float sbx0[NT], sbx1[NT], sby0[NT], sby1[NT];
    __shared__ int   scell[NT];
    __shared__ unsigned s_inv[2];
    __shared__ float swarp[8];
    __shared__ int   s_last;

    const int bid  = blockIdx.x;
    const int b    = bid >> 2;
    const int tid  = threadIdx.x;
    const int cell = ((bid & 3) << 8) | tid;       // 0..1023

    // ---- 1) issue the 19 prediction loads FIRST: DRAM latency overlaps staging
    const float* ob = out + (size_t)(b * CH) * NCELL + cell;
    float raw[2 * K + 1];
    #pragma unroll
    for (int c = 0; c < 2 * K + 1; c++) raw[c] = ob[c * NCELL];

    // ---- 2) stage targets (coalesced), pre-scaled to pixels
    const float* tb = tgt + (size_t)b * (NT * NLAB);
    for (int idx = tid; idx < NT * 2 * K; idx += 256) {
        int t = idx / (2 * K), c = idx - t * (2 * K);
        float v = tb[t * NLAB + 1 + c];
        if (c & 1) sY[t][c >> 1] = v * IMH;
        else       sX[t][c >> 1] = v * IMW;
    }
    // validity prefix via ballot (x0 != 0), two full warps
    if (tid < 64) {
        bool v = (tid < NT) && (tb[tid * NLAB + 1] != 0.0f);
        unsigned m = __ballot_sync(0xffffffffu, v);
        if ((tid & 31) == 0) s_inv[tid >> 5] = ~m;
    }
    __syncthreads();

    // ---- 3) per-target bbox + cell index
    if (tid < NT) {
        float mnx = sX[tid][0], mxx = mnx, mny = sY[tid][0], mxy = mny;
        #pragma unroll
        for (int k = 1; k < K; k++) {
            mnx = fminf(mnx, sX[tid][k]); mxx = fmaxf(mxx, sX[tid][k]);
            mny = fminf(mny, sY[tid][k]); mxy = fmaxf(mxy, sY[tid][k]);
        }
        sbx0[tid] = mnx; sbx1[tid] = mxx; sby0[tid] = mny; sby1[tid] = mxy;
        int gi0 = (int)floorf(sX[tid][0] * (1.0f / CELLW));
        int gj0 = (int)floorf(sY[tid][0] * (1.0f / CELLH));
        scell[tid] = (gi0 >= 0 && gi0 < NW && gj0 >= 0 && gj0 < NH)
                         ? gj0 * NW + gi0 : -1;
    }
    __syncthreads();

    const unsigned inv0 = s_inv[0], inv1 = s_inv[1];
    const int nv = inv0 ? (__ffs(inv0) - 1) : (inv1 ? 31 + __ffs(inv1) : 64);
    const bool do_conf = (epoch_p ? __ldg(epoch_p) : 20) > 15;
    const float i_f = (float)(cell & (NW - 1));
    const float j_f = (float)(cell >> 5);

    // ---- 4) predictions in pixel space
    raw[0]      = 1.0f / (1.0f + __expf(-raw[0]));
    raw[1]      = 1.0f / (1.0f + __expf(-raw[1]));
    float confp = 1.0f / (1.0f + __expf(-raw[2 * K]));

    float px[K], py[K];
    float pminx = 1e30f, pmaxx = -1e30f, pminy = 1e30f, pmaxy = -1e30f;
    #pragma unroll
    for (int k = 0; k < K; k++) {
        px[k] = (raw[2 * k]     + i_f) * CELLW;
        py[k] = (raw[2 * k + 1] + j_f) * CELLH;
        pminx = fminf(pminx, px[k]); pmaxx = fmaxf(pmaxx, px[k]);
        pminy = fminf(pminy, py[k]); pmaxy = fmaxf(pmaxy, py[k]);
    }

    const float inv_denK = (1.0f / (float)K) / (__expf(2.0f) - 1.0f + 1e-5f);

    // ---- 5) silent-zone max over valid targets, exact-zero bbox prune
    float cur = 0.0f, accHit = 0.0f;
    int thit = -1;
    for (int t = 0; t < nv; t++) {
        bool hit = (scell[t] == cell);
        if (hit) thit = t;
        float sepx = fmaxf(sbx0[t] - pmaxx, pminx - sbx1[t]);
        float sepy = fmaxf(sby0[t] - pmaxy, pminy - sby1[t]);
        if (sepx >= THR || sepy >= THR) continue;   // every corner dist >= THR
        float acc = 0.0f;
        #pragma unroll
        for (int k = 0; k < K; k++) {
            float dx = sX[t][k] - px[k];
            float dy = sY[t][k] - py[k];
            float d2 = fmaf(dx, dx, dy * dy);
            if (d2 < THR * THR)
                acc += __expf(2.0f - sqrtf(d2) * (2.0f / THR)) - 1.0f;
        }
        if (hit) accHit = acc;   // reuse as conf_gt (hit target never pruned here)
        cur = fmaxf(cur, acc);
    }
    cur *= inv_denK;

    // ---- 6) per-cell loss
    float lcl = 0.0f;
    if (thit >= 0) {
        float gx0 = floorf(sX[thit][0] * (1.0f / CELLW));
        float gy0 = floorf(sY[thit][0] * (1.0f / CELLH));
        #pragma unroll
        for (int k = 0; k < K; k++) {
            float xs_k = px[k] * (1.0f / CELLW) - i_f;       // recover xs
            float ys_k = py[k] * (1.0f / CELLH) - j_f;
            float ex = xs_k - (sX[thit][k] * (1.0f / CELLW) - gx0);
            float ey = ys_k - (sY[thit][k] * (1.0f / CELLH) - gy0);
            lcl += 0.5f * (ex * ex + ey * ey);
        }
        if (do_conf) {
            float e = confp - accHit * inv_denK;
            lcl += 0.5f * OBJ * e * e;
        }
    } else if (do_conf) {
        if (cur <= SIL) lcl += 0.5f * confp * confp;   // NOOBJ, tconf = 0
    }

    // ---- 7) block reduce -> partial; last block reduces 256 partials
    #pragma unroll
    for (int o = 16; o > 0; o >>= 1)
        lcl += __shfl_xor_sync(0xffffffffu, lcl, o);
    if ((tid & 31) == 0) swarp[tid >> 5] = lcl;
    __syncthreads();
    if (tid < 8) {
        float v = swarp[tid];
        #pragma unroll
        for (int o = 4; o > 0; o >>= 1)
            v += __shfl_xor_sync(0xffu, v, o);
        if (tid == 0) {
            g_partials[bid] = v;
            __threadfence();
            unsigned old = atomicAdd(&g_count, 1);
            s_last = (old == NBLK - 1) ? 1 : 0;
        }
    }
    __syncthreads();
    if (s_last) {
        float v = g_partials[tid];
        #pragma unroll
        for (int o = 16; o > 0; o >>= 1)
            v += __shfl_xor_sync(0xffffffffu, v, o);
        if ((tid & 31) == 0) swarp[tid >> 5] = v;
        __syncthreads();
        if (tid < 8) {
            float w = swarp[tid];
            #pragma unroll
            for (int o = 4; o > 0; o >>= 1)
                w += __shfl_xor_sync(0xffu, w, o);
            if (tid == 0) {
                loss[0]  = w;
                g_count  = 0;   // reset for next graph replay (determinism)
            }
        }
    }
}

extern "C" void kernel_launch(void* const* d_in, const int* in_sizes, int n_in,
                              void* d_out, int out_size)
{
    const float* output = (const float*)d_in[0];
    const float* target = (const float*)d_in[1];
    const int*   epoch  = (n_in > 2) ? (const int*)d_in[2] : nullptr;
    float* loss = (float*)d_out;

    region_loss_kernel<<<NBLK, 256>>>(output, target, epoch, loss);
    (void)in_sizes; (void)out_size;
}